// round 8
// baseline (speedup 1.0000x reference)
#include <cuda_runtime.h>
#include <math.h>

#define N_NODES   100000
#define N_EDGES   1600000
#define F_DIM     64
#define C_CLS     10
#define G_GRAPHS  512
#define CAP       64           // max in-degree (Poisson mean 16; P(>64) ~ 1e-20)

// Scratch (device globals: no runtime allocation allowed)
__device__ float g_h0[N_NODES * F_DIM];
__device__ float g_h1[N_NODES * F_DIM];
__device__ float g_dinv[N_NODES];
__device__ int   g_cnt_in[N_NODES];
__device__ int2  g_adj[(size_t)N_NODES * CAP];   // {src, weight bits}
__device__ int   g_dummy;

// ---------------------------------------------------------------------------
__global__ void zero_cnt_kernel() {
    int i = blockIdx.x * blockDim.x + threadIdx.x;
    if (i < N_NODES) g_cnt_in[i] = 0;
}

// One atomic per edge: drop edge into destination node's bucket (raw ew).
__global__ void bucket_kernel(const int* __restrict__ row,
                              const int* __restrict__ col,
                              const float* __restrict__ ew) {
    int stride = gridDim.x * blockDim.x;
    for (int e = blockIdx.x * blockDim.x + threadIdx.x; e < N_EDGES; e += stride) {
        int c = col[e];
        int i = atomicAdd(&g_cnt_in[c], 1);
        if (i < CAP)
            g_adj[(size_t)c * CAP + i] = make_int2(row[e], __float_as_int(ew[e]));
    }
}

// Spacer: pads the launch sequence so the pool_head PROBE lands in the ncu
// capture slot (launch #4).
__global__ void spacer_kernel() {
    if (threadIdx.x == 0 && blockIdx.x == 0) g_dummy = 0;
}

// deg[c] = 1 (self loop) + sum of raw in-edge weights; dinv = rsqrt (guarded).
__global__ void deg_dinv_kernel() {
    int t = blockIdx.x * blockDim.x + threadIdx.x;
    int n = t >> 5;
    int lane = t & 31;
    if (n >= N_NODES) return;
    int cnt = min(g_cnt_in[n], CAP);
    const int2* adj = g_adj + (size_t)n * CAP;
    float d = 0.0f;
    for (int k = lane; k < cnt; k += 32)
        d += __int_as_float(adj[k].y);
#pragma unroll
    for (int off = 16; off > 0; off >>= 1)
        d += __shfl_xor_sync(0xFFFFFFFFu, d, off);
    if (lane == 0) {
        d += 1.0f;  // self loop
        g_dinv[n] = (d > 0.0f) ? rsqrtf(d) : 0.0f;
    }
}

// ---------------------------------------------------------------------------
// Gather hop. 2 nodes per warp; half-warp = 16 lanes x float4 = one node row.
template <bool FUSE_NORM>
__global__ void hop_kernel(const float* __restrict__ hin,
                           float* __restrict__ hout) {
    int t = blockIdx.x * blockDim.x + threadIdx.x;
    int warp = t >> 5;
    int lane = t & 31;
    int n = warp * 2 + (lane >> 4);
    int sub = lane & 15;                 // float4 index within node row
    if (n >= N_NODES) return;

    const float4* __restrict__ hin4 = reinterpret_cast<const float4*>(hin);
    float4* __restrict__ hout4 = reinterpret_cast<float4*>(hout);

    float dv = g_dinv[n];
    float sl = dv * dv;                  // self-loop weight
    float4 acc = hin4[(size_t)n * 16 + sub];
    acc.x *= sl; acc.y *= sl; acc.z *= sl; acc.w *= sl;

    int cnt = min(g_cnt_in[n], CAP);
    int2* adj = g_adj + (size_t)n * CAP;

    for (int k = 0; k < cnt; k += 4) {
        int4 p0 = *reinterpret_cast<const int4*>(adj + k);
        int4 p1 = *reinterpret_cast<const int4*>(adj + k + 2);
        int   s[4]  = { p0.x, p0.z, p1.x, p1.z };
        float w[4]  = { __int_as_float(p0.y), __int_as_float(p0.w),
                        __int_as_float(p1.y), __int_as_float(p1.w) };

        float4 u[4];
        float wv[4];
#pragma unroll
        for (int i = 0; i < 4; i++) {
            unsigned su = (unsigned)s[i];
            int src = (su < (unsigned)N_NODES) ? (int)su : 0;
            u[i] = hin4[(size_t)src * 16 + sub];      // 4 gathers in flight
            wv[i] = FUSE_NORM ? (g_dinv[src] * w[i] * dv) : w[i];
        }
#pragma unroll
        for (int i = 0; i < 4; i++) {
            if (k + i < cnt) {
                acc.x = fmaf(wv[i], u[i].x, acc.x);
                acc.y = fmaf(wv[i], u[i].y, acc.y);
                acc.z = fmaf(wv[i], u[i].z, acc.z);
                acc.w = fmaf(wv[i], u[i].w, acc.w);
                if (FUSE_NORM && sub == 0)
                    adj[k + i].y = __float_as_int(wv[i]);  // persist for hops 2-3
            }
        }
    }
    hout4[(size_t)n * 16 + sub] = acc;
}

// ---------------------------------------------------------------------------
// Fused pool + head. batch sorted -> graph g is a contiguous node range.
__global__ void pool_head_kernel(const float* __restrict__ h,
                                 const int* __restrict__ batch,
                                 const float* __restrict__ conv_w,
                                 const float* __restrict__ conv_b,
                                 const float* __restrict__ lin1_w,
                                 const float* __restrict__ lin1_b,
                                 const float* __restrict__ lin2_w,
                                 const float* __restrict__ lin2_b,
                                 float* __restrict__ out) {
    int g = blockIdx.x;
    int j = threadIdx.x & 63;       // feature
    int chunk = threadIdx.x >> 6;   // 0..3

    __shared__ int s_bounds[2];
    if (threadIdx.x < 2) {
        int target = g + threadIdx.x;   // lower_bound(batch, target)
        int lo = 0, hiN = N_NODES;
        while (lo < hiN) {
            int mid = (lo + hiN) >> 1;
            if (batch[mid] < target) lo = mid + 1; else hiN = mid;
        }
        s_bounds[threadIdx.x] = lo;
    }
    __syncthreads();
    int lo = s_bounds[0];
    int hi = s_bounds[1];

    float s = 0.0f;
    for (int i = lo + chunk; i < hi; i += 4) s += h[(size_t)i * F_DIM + j];

    __shared__ float s_part[4][F_DIM];
    s_part[chunk][j] = s;
    __syncthreads();

    __shared__ float s_mean[F_DIM];
    __shared__ float s_h1[F_DIM];
    __shared__ float s_h2[F_DIM];
    __shared__ float s_o[C_CLS];

    if (chunk == 0) {
        float cnt = (float)(hi - lo);
        float tot = s_part[0][j] + s_part[1][j] + s_part[2][j] + s_part[3][j];
        s_mean[j] = tot / fmaxf(cnt, 1.0f);
    }
    __syncthreads();

    if (chunk == 0) {
        float acc = conv_b[j];
#pragma unroll
        for (int f = 0; f < F_DIM; f++) acc += s_mean[f] * conv_w[f * F_DIM + j];
        s_h1[j] = acc;
    }
    __syncthreads();

    if (chunk == 0) {
        float acc = lin1_b[j];
#pragma unroll
        for (int f = 0; f < F_DIM; f++) acc += s_h1[f] * lin1_w[f * F_DIM + j];
        s_h2[j] = fmaxf(acc, 0.0f);
    }
    __syncthreads();

    if (chunk == 0 && j < C_CLS) {
        float acc = lin2_b[j];
#pragma unroll
        for (int f = 0; f < F_DIM; f++) acc += s_h2[f] * lin2_w[f * C_CLS + j];
        s_o[j] = acc;
    }
    __syncthreads();

    if (chunk == 0 && j < C_CLS) {
        float m = -1e30f;
#pragma unroll
        for (int c = 0; c < C_CLS; c++) m = fmaxf(m, s_o[c]);
        float sum = 0.0f;
#pragma unroll
        for (int c = 0; c < C_CLS; c++) sum += __expf(s_o[c] - m);
        out[g * C_CLS + j] = s_o[j] - m - __logf(sum);
    }
}

// ---------------------------------------------------------------------------
extern "C" void kernel_launch(void* const* d_in, const int* in_sizes, int n_in,
                              void* d_out, int out_size) {
    const float* x      = (const float*)d_in[0];   // [N, 64]
    const int*   eidx   = (const int*)d_in[1];     // [2, E]
    const float* ew     = (const float*)d_in[2];   // [E]
    const int*   batch  = (const int*)d_in[3];     // [N], sorted
    const float* conv_w = (const float*)d_in[4];
    const float* conv_b = (const float*)d_in[5];
    const float* lin1_w = (const float*)d_in[6];
    const float* lin1_b = (const float*)d_in[7];
    const float* lin2_w = (const float*)d_in[8];
    const float* lin2_b = (const float*)d_in[9];
    float* out = (float*)d_out;                    // [512, 10]

    const int* row = eidx;            // edge_index[0]
    const int* col = eidx + N_EDGES;  // edge_index[1]

    const int TPB = 256;
    const int nblk_N = (N_NODES + TPB - 1) / TPB;
    const int nblk_W = (N_NODES * 32 + TPB - 1) / TPB;  // warp per node
    const int nblk_H = (N_NODES * 16 + TPB - 1) / TPB;  // 2 nodes per warp

    // 1. zero counters
    zero_cnt_kernel<<<nblk_N, TPB>>>();
    // 2. build in-adjacency buckets
    bucket_kernel<<<1184, TPB>>>(row, col, ew);
    // 3. spacer (pads probe into ncu capture slot #4)
    spacer_kernel<<<1, 32>>>();
    // 4. PROBE: pool_head on stale g_h0 (steady-state-identical data; its
    //    d_out write is overwritten by the final pool_head) <- NCU SLOT
    pool_head_kernel<<<G_GRAPHS, TPB>>>(g_h0, batch, conv_w, conv_b,
                                        lin1_w, lin1_b, lin2_w, lin2_b, out);
    // 5. degrees -> dinv
    deg_dinv_kernel<<<nblk_W, TPB>>>();
    // 6. hop 1 (fused normalization, writes wv back)
    hop_kernel<true><<<nblk_H, TPB>>>(x, g_h0);
    // 7-8. hops 2,3
    hop_kernel<false><<<nblk_H, TPB>>>(g_h0, g_h1);
    hop_kernel<false><<<nblk_H, TPB>>>(g_h1, g_h0);
    // 9-11. EXPERIMENT: three extra hops into dead buffer g_h1.
    //       Wall delta vs R5 = 3*t_hop_inloop + t_pool_probe.
    hop_kernel<false><<<nblk_H, TPB>>>(g_h0, g_h1);
    hop_kernel<false><<<nblk_H, TPB>>>(g_h0, g_h1);
    hop_kernel<false><<<nblk_H, TPB>>>(g_h0, g_h1);
    // 12. final (authoritative) pool + head
    pool_head_kernel<<<G_GRAPHS, TPB>>>(g_h0, batch, conv_w, conv_b,
                                        lin1_w, lin1_b, lin2_w, lin2_b, out);
}

// round 11
// speedup vs baseline: 59.0068x; 59.0068x over previous
#include <cuda_runtime.h>
#include <math.h>

#define N_NODES   100000
#define N_EDGES   1600000
#define F_DIM     64
#define C_CLS     10
#define G_GRAPHS  512
#define CAP       64        // max in-degree (Poisson mean 16; P(>64) ~ 1e-20)
#define NBLK      444       // 148 SMs x 3 co-resident blocks (guaranteed)
#define TPB       256
#define NWARPS    (NBLK * TPB / 32)

// Scratch (device globals: no runtime allocation allowed)
__device__ float    g_h0[N_NODES * F_DIM];
__device__ float    g_h1[N_NODES * F_DIM];
__device__ float    g_dinv[N_NODES];
__device__ int      g_cnt_in[N_NODES];
__device__ int2     g_adj[(size_t)N_NODES * CAP];   // {src, raw weight bits}
__device__ float    g_s[G_GRAPHS * F_DIM];
__device__ unsigned g_ticket;   // monotonic barrier counter; NEVER reset.

static __device__ __forceinline__ void red_add_v4(float* dst, float4 v) {
    asm volatile("red.global.add.v4.f32 [%0], {%1, %2, %3, %4};"
                 :: "l"(dst), "f"(v.x), "f"(v.y), "f"(v.z), "f"(v.w)
                 : "memory");
}

// Grid-wide barrier, monotonic ticket counter (no reset across graph replays).
// RELEASE: every thread fences (drains its stores/REDs) before the block
// arrives. ACQUIRE: every thread fences after the wait (gpu-scope fence
// invalidates this SM's L1D) before the next phase's loads.
static __device__ __forceinline__ void grid_barrier() {
    __threadfence();                 // release (all threads)
    __syncthreads();
    if (threadIdx.x == 0) {
        unsigned t = atomicAdd(&g_ticket, 1u);
        unsigned target = (t / NBLK + 1u) * NBLK;
        while (atomicAdd(&g_ticket, 0u) < target) __nanosleep(64);
    }
    __syncthreads();
    __threadfence();                 // acquire (all threads)
}

// ---------------------------------------------------------------------------
// Hop as a device function. Half-warp (16 lanes x float4) = one 64-float node
// row; 2 nodes per warp per iteration; 4-deep gather pipeline.
// Normalization on the fly: wv = dinv[src] * ew * dinv[dst].
// POOL: instead of writing h_out, red-add the row into g_s[batch[n]].
template <bool POOL>
static __device__ void hop_phase(const float* __restrict__ hin,
                                 float* __restrict__ hout,
                                 const int* __restrict__ batch) {
    int gwarp = (blockIdx.x * TPB + threadIdx.x) >> 5;
    int lane = threadIdx.x & 31;
    int half = lane >> 4;
    int sub = lane & 15;
    const float4* __restrict__ hin4 = reinterpret_cast<const float4*>(hin);
    float4* __restrict__ hout4 = reinterpret_cast<float4*>(hout);

    for (int base = gwarp * 2; base < N_NODES; base += NWARPS * 2) {
        int n = base + half;   // N_NODES even -> both halves always valid

        float dv = g_dinv[n];
        float sl = dv * dv;                    // self-loop weight
        float4 acc = hin4[(size_t)n * 16 + sub];
        acc.x *= sl; acc.y *= sl; acc.z *= sl; acc.w *= sl;

        int cnt = min(g_cnt_in[n], CAP);
        const int2* adj = g_adj + (size_t)n * CAP;

        for (int k = 0; k < cnt; k += 4) {
            int4 p0 = *reinterpret_cast<const int4*>(adj + k);
            int4 p1 = *reinterpret_cast<const int4*>(adj + k + 2);
            int   s[4] = { p0.x, p0.z, p1.x, p1.z };
            float w[4] = { __int_as_float(p0.y), __int_as_float(p0.w),
                           __int_as_float(p1.y), __int_as_float(p1.w) };

            float4 u[4];
            float wv[4];
#pragma unroll
            for (int i = 0; i < 4; i++) {
                unsigned su = (unsigned)s[i];
                int src = (su < (unsigned)N_NODES) ? (int)su : 0;
                u[i] = hin4[(size_t)src * 16 + sub];    // 4 gathers in flight
                wv[i] = g_dinv[src] * w[i] * dv;
            }
#pragma unroll
            for (int i = 0; i < 4; i++) {
                if (k + i < cnt) {
                    acc.x = fmaf(wv[i], u[i].x, acc.x);
                    acc.y = fmaf(wv[i], u[i].y, acc.y);
                    acc.z = fmaf(wv[i], u[i].z, acc.z);
                    acc.w = fmaf(wv[i], u[i].w, acc.w);
                }
            }
        }

        if (POOL) {
            int b = batch[n];
            red_add_v4(&g_s[b * F_DIM + sub * 4], acc);
        } else {
            hout4[(size_t)n * 16 + sub] = acc;
        }
    }
}

// ---------------------------------------------------------------------------
// ONE persistent kernel: all phases, separated by grid barriers.
__global__ void __launch_bounds__(TPB, 3)
sgc_persistent_kernel(const float* __restrict__ x,
                      const int* __restrict__ eidx,
                      const float* __restrict__ ew,
                      const int* __restrict__ batch,
                      const float* __restrict__ conv_w,
                      const float* __restrict__ conv_b,
                      const float* __restrict__ lin1_w,
                      const float* __restrict__ lin1_b,
                      const float* __restrict__ lin2_w,
                      const float* __restrict__ lin2_b,
                      float* __restrict__ out) {
    const int tid = blockIdx.x * TPB + threadIdx.x;
    const int stride = NBLK * TPB;
    const int* row = eidx;             // edge_index[0]
    const int* col = eidx + N_EDGES;   // edge_index[1]

    // ---- phase 0: zero counters + pool accumulators ----
    for (int i = tid; i < N_NODES; i += stride) g_cnt_in[i] = 0;
    for (int i = tid; i < G_GRAPHS * F_DIM; i += stride) g_s[i] = 0.0f;
    grid_barrier();

    // ---- phase 1: build in-adjacency buckets (raw weights) ----
    for (int e = tid; e < N_EDGES; e += stride) {
        int c = col[e];
        int i = atomicAdd(&g_cnt_in[c], 1);
        if (i < CAP)
            g_adj[(size_t)c * CAP + i] = make_int2(row[e], __float_as_int(ew[e]));
    }
    grid_barrier();

    // ---- phase 2: degrees -> dinv (warp per node, shuffle reduce) ----
    {
        int gwarp = tid >> 5;
        int lane = threadIdx.x & 31;
        for (int n = gwarp; n < N_NODES; n += NWARPS) {
            int cnt = min(g_cnt_in[n], CAP);
            const int2* adj = g_adj + (size_t)n * CAP;
            float d = 0.0f;
            for (int k = lane; k < cnt; k += 32)
                d += __int_as_float(adj[k].y);
#pragma unroll
            for (int off = 16; off > 0; off >>= 1)
                d += __shfl_xor_sync(0xFFFFFFFFu, d, off);
            d += 1.0f;   // self loop
            if (lane == 0)
                g_dinv[n] = (d > 0.0f) ? rsqrtf(d) : 0.0f;
        }
    }
    grid_barrier();

    // ---- phases 3-5: K=3 propagation; last hop fuses the mean-pool sum ----
    hop_phase<false>(x,    g_h0, batch);
    grid_barrier();
    hop_phase<false>(g_h0, g_h1, batch);
    grid_barrier();
    hop_phase<true >(g_h1, g_h0 /*unused*/, batch);
    grid_barrier();

    // ---- phase 6: head. GRID-STRIDE over graphs (NBLK=444 < G_GRAPHS=512:
    //      the Round-9/10 bug left graphs 444..511 unwritten -> exactly the
    //      observed rel_err sqrt(68/512)=0.3644). Blocks 0..67 do 2 graphs.
    for (int g = blockIdx.x; g < G_GRAPHS; g += NBLK) {
        int j = threadIdx.x;

        __shared__ int   s_bounds[2];
        __shared__ float s_bufA[F_DIM];
        __shared__ float s_bufB[F_DIM];
        __shared__ float s_o[C_CLS];

        if (j < 2) {  // lower_bound(batch, g) / lower_bound(batch, g+1)
            int target = g + j;
            int lo = 0, hiN = N_NODES;
            while (lo < hiN) {
                int mid = (lo + hiN) >> 1;
                if (batch[mid] < target) lo = mid + 1; else hiN = mid;
            }
            s_bounds[j] = lo;
        }
        __syncthreads();

        if (j < F_DIM) {
            float cnt = (float)(s_bounds[1] - s_bounds[0]);
            s_bufA[j] = g_s[g * F_DIM + j] / fmaxf(cnt, 1.0f);   // mean
        }
        __syncthreads();

        if (j < F_DIM) {
            float acc = conv_b[j];
#pragma unroll
            for (int f = 0; f < F_DIM; f++) acc += s_bufA[f] * conv_w[f * F_DIM + j];
            s_bufB[j] = acc;                                     // conv out
        }
        __syncthreads();

        if (j < F_DIM) {
            float acc = lin1_b[j];
#pragma unroll
            for (int f = 0; f < F_DIM; f++) acc += s_bufB[f] * lin1_w[f * F_DIM + j];
            s_bufA[j] = fmaxf(acc, 0.0f);                        // relu(lin1)
        }
        __syncthreads();

        if (j < C_CLS) {
            float acc = lin2_b[j];
#pragma unroll
            for (int f = 0; f < F_DIM; f++) acc += s_bufA[f] * lin2_w[f * C_CLS + j];
            s_o[j] = acc;
        }
        __syncthreads();

        if (j < C_CLS) {
            float m = -1e30f;
#pragma unroll
            for (int c = 0; c < C_CLS; c++) m = fmaxf(m, s_o[c]);
            float sum = 0.0f;
#pragma unroll
            for (int c = 0; c < C_CLS; c++) sum += __expf(s_o[c] - m);
            out[g * C_CLS + j] = s_o[j] - m - __logf(sum);
        }
        __syncthreads();   // protect smem reuse across loop iterations
    }
}

// ---------------------------------------------------------------------------
extern "C" void kernel_launch(void* const* d_in, const int* in_sizes, int n_in,
                              void* d_out, int out_size) {
    const float* x      = (const float*)d_in[0];   // [N, 64]
    const int*   eidx   = (const int*)d_in[1];     // [2, E]
    const float* ew     = (const float*)d_in[2];   // [E]
    const int*   batch  = (const int*)d_in[3];     // [N], sorted
    const float* conv_w = (const float*)d_in[4];
    const float* conv_b = (const float*)d_in[5];
    const float* lin1_w = (const float*)d_in[6];
    const float* lin1_b = (const float*)d_in[7];
    const float* lin2_w = (const float*)d_in[8];
    const float* lin2_b = (const float*)d_in[9];
    float* out = (float*)d_out;                    // [512, 10]

    sgc_persistent_kernel<<<NBLK, TPB>>>(x, eidx, ew, batch,
                                         conv_w, conv_b, lin1_w, lin1_b,
                                         lin2_w, lin2_b, out);
}

// round 12
// speedup vs baseline: 60.6188x; 1.0273x over previous
#include <cuda_runtime.h>
#include <math.h>

#define N_NODES   100000
#define N_EDGES   1600000
#define F_DIM     64
#define C_CLS     10
#define G_GRAPHS  512
#define CAP       64        // max in-degree (Poisson mean 16; P(>64) ~ 1e-20)
#define NBLK      444       // 148 SMs x 3 co-resident blocks (guaranteed)
#define TPB       256
#define NWARPS    (NBLK * TPB / 32)

// Scratch (device globals: no runtime allocation allowed)
__device__ float    g_h0[N_NODES * F_DIM];
__device__ float    g_h1[N_NODES * F_DIM];
__device__ float    g_dinv[N_NODES];
__device__ int      g_cnt_in[N_NODES];
__device__ int2     g_adj[(size_t)N_NODES * CAP];   // {src, raw weight bits}
__device__ float    g_s[G_GRAPHS * F_DIM];
__device__ unsigned g_ticket;   // monotonic barrier counter; NEVER reset.

static __device__ __forceinline__ void red_add_v4(float* dst, float4 v) {
    asm volatile("red.global.add.v4.f32 [%0], {%1, %2, %3, %4};"
                 :: "l"(dst), "f"(v.x), "f"(v.y), "f"(v.z), "f"(v.w)
                 : "memory");
}

// Grid-wide barrier, monotonic ticket counter (no reset across graph replays).
static __device__ __forceinline__ void grid_barrier() {
    __threadfence();                 // release (all threads)
    __syncthreads();
    if (threadIdx.x == 0) {
        unsigned t = atomicAdd(&g_ticket, 1u);
        unsigned target = (t / NBLK + 1u) * NBLK;
        while (atomicAdd(&g_ticket, 0u) < target) __nanosleep(32);
    }
    __syncthreads();
    __threadfence();                 // acquire (all threads)
}

// ---------------------------------------------------------------------------
// Hop in SCALED representation: input is h_hat = dinv .* h.
//   acc      = h_hat[c] + sum_e ew * h_hat[src]       (per-edge: ew + gather only)
//   !POOL:   h_hat_out[c] = dinv[c]^2 * acc           (stays scaled)
//   POOL:    h_final[c]   = dinv[c]   * acc  -> red-add into g_s[batch[c]]
// Half-warp (16 lanes x float4) = one node row; 2 nodes per warp; 4-deep
// gather pipeline; overshoot entries get w=0 so all FMAs are unpredicated.
template <bool POOL>
static __device__ void hop_phase(const float* __restrict__ hin,
                                 float* __restrict__ hout,
                                 const int* __restrict__ batch) {
    int gwarp = (blockIdx.x * TPB + threadIdx.x) >> 5;
    int lane = threadIdx.x & 31;
    int half = lane >> 4;
    int sub = lane & 15;
    const float4* __restrict__ hin4 = reinterpret_cast<const float4*>(hin);
    float4* __restrict__ hout4 = reinterpret_cast<float4*>(hout);

    for (int base = gwarp * 2; base < N_NODES; base += NWARPS * 2) {
        int n = base + half;   // N_NODES even -> both halves always valid

        float dv = g_dinv[n];
        float4 acc = hin4[(size_t)n * 16 + sub];   // self contribution h_hat[c]

        int cnt = min(g_cnt_in[n], CAP);
        const int2* adj = g_adj + (size_t)n * CAP;

        for (int k = 0; k < cnt; k += 4) {
            int4 p0 = *reinterpret_cast<const int4*>(adj + k);
            int4 p1 = *reinterpret_cast<const int4*>(adj + k + 2);
            int   s[4] = { p0.x, p0.z, p1.x, p1.z };
            float w[4] = { __int_as_float(p0.y), __int_as_float(p0.w),
                           __int_as_float(p1.y), __int_as_float(p1.w) };

            float4 u[4];
#pragma unroll
            for (int i = 0; i < 4; i++) {
                if (k + i >= cnt) w[i] = 0.0f;          // neutralize overshoot
                unsigned su = (unsigned)s[i];
                int src = (su < (unsigned)N_NODES) ? (int)su : 0;
                u[i] = hin4[(size_t)src * 16 + sub];    // 4 gathers in flight
            }
#pragma unroll
            for (int i = 0; i < 4; i++) {
                acc.x = fmaf(w[i], u[i].x, acc.x);
                acc.y = fmaf(w[i], u[i].y, acc.y);
                acc.z = fmaf(w[i], u[i].z, acc.z);
                acc.w = fmaf(w[i], u[i].w, acc.w);
            }
        }

        float sc = POOL ? dv : (dv * dv);
        acc.x *= sc; acc.y *= sc; acc.z *= sc; acc.w *= sc;

        if (POOL) {
            int b = batch[n];
            red_add_v4(&g_s[b * F_DIM + sub * 4], acc);
        } else {
            hout4[(size_t)n * 16 + sub] = acc;
        }
    }
}

// ---------------------------------------------------------------------------
// ONE persistent kernel: all phases, separated by grid barriers.
__global__ void __launch_bounds__(TPB, 3)
sgc_persistent_kernel(const float* __restrict__ x,
                      const int* __restrict__ eidx,
                      const float* __restrict__ ew,
                      const int* __restrict__ batch,
                      const float* __restrict__ conv_w,
                      const float* __restrict__ conv_b,
                      const float* __restrict__ lin1_w,
                      const float* __restrict__ lin1_b,
                      const float* __restrict__ lin2_w,
                      const float* __restrict__ lin2_b,
                      float* __restrict__ out) {
    const int tid = blockIdx.x * TPB + threadIdx.x;
    const int stride = NBLK * TPB;
    const int* row = eidx;             // edge_index[0]
    const int* col = eidx + N_EDGES;   // edge_index[1]

    // ---- phase 0: zero counters + pool accumulators ----
    for (int i = tid; i < N_NODES; i += stride) g_cnt_in[i] = 0;
    for (int i = tid; i < G_GRAPHS * F_DIM; i += stride) g_s[i] = 0.0f;
    grid_barrier();

    // ---- phase 1: build in-adjacency buckets (raw weights) ----
    for (int e = tid; e < N_EDGES; e += stride) {
        int c = col[e];
        int i = atomicAdd(&g_cnt_in[c], 1);
        if (i < CAP)
            g_adj[(size_t)c * CAP + i] = make_int2(row[e], __float_as_int(ew[e]));
    }
    grid_barrier();

    // ---- phase 2: degrees -> dinv, FUSED with prescale h_hat0 = dinv * x
    //      (warp per node; after xor-reduce every lane holds d) ----
    {
        int gwarp = tid >> 5;
        int lane = threadIdx.x & 31;
        const float2* __restrict__ x2 = reinterpret_cast<const float2*>(x);
        float2* __restrict__ hp2 = reinterpret_cast<float2*>(g_h1);
        for (int n = gwarp; n < N_NODES; n += NWARPS) {
            int cnt = min(g_cnt_in[n], CAP);
            const int2* adj = g_adj + (size_t)n * CAP;
            float d = 0.0f;
            for (int k = lane; k < cnt; k += 32)
                d += __int_as_float(adj[k].y);
#pragma unroll
            for (int off = 16; off > 0; off >>= 1)
                d += __shfl_xor_sync(0xFFFFFFFFu, d, off);
            d += 1.0f;   // self loop
            float dv = (d > 0.0f) ? rsqrtf(d) : 0.0f;
            if (lane == 0) g_dinv[n] = dv;
            // prescale: 64 floats = 32 x float2, one per lane
            float2 v = x2[(size_t)n * 32 + lane];
            v.x *= dv; v.y *= dv;
            hp2[(size_t)n * 32 + lane] = v;
        }
    }
    grid_barrier();

    // ---- phases 3-5: K=3 propagation in scaled rep; hop 3 fuses pool ----
    hop_phase<false>(g_h1, g_h0, batch);   // h_hat0 -> h_hat1
    grid_barrier();
    hop_phase<false>(g_h0, g_h1, batch);   // h_hat1 -> h_hat2
    grid_barrier();
    hop_phase<true >(g_h1, g_h0 /*unused*/, batch);  // h_hat2 -> pooled h3
    grid_barrier();

    // ---- phase 6: head, grid-stride over graphs ----
    for (int g = blockIdx.x; g < G_GRAPHS; g += NBLK) {
        int j = threadIdx.x;

        __shared__ int   s_bounds[2];
        __shared__ float s_bufA[F_DIM];
        __shared__ float s_bufB[F_DIM];
        __shared__ float s_o[C_CLS];

        if (j < 2) {  // lower_bound(batch, g) / lower_bound(batch, g+1)
            int target = g + j;
            int lo = 0, hiN = N_NODES;
            while (lo < hiN) {
                int mid = (lo + hiN) >> 1;
                if (batch[mid] < target) lo = mid + 1; else hiN = mid;
            }
            s_bounds[j] = lo;
        }
        __syncthreads();

        if (j < F_DIM) {
            float cnt = (float)(s_bounds[1] - s_bounds[0]);
            s_bufA[j] = g_s[g * F_DIM + j] / fmaxf(cnt, 1.0f);   // mean
        }
        __syncthreads();

        if (j < F_DIM) {
            float acc = conv_b[j];
#pragma unroll
            for (int f = 0; f < F_DIM; f++) acc += s_bufA[f] * conv_w[f * F_DIM + j];
            s_bufB[j] = acc;                                     // conv out
        }
        __syncthreads();

        if (j < F_DIM) {
            float acc = lin1_b[j];
#pragma unroll
            for (int f = 0; f < F_DIM; f++) acc += s_bufB[f] * lin1_w[f * F_DIM + j];
            s_bufA[j] = fmaxf(acc, 0.0f);                        // relu(lin1)
        }
        __syncthreads();

        if (j < C_CLS) {
            float acc = lin2_b[j];
#pragma unroll
            for (int f = 0; f < F_DIM; f++) acc += s_bufA[f] * lin2_w[f * C_CLS + j];
            s_o[j] = acc;
        }
        __syncthreads();

        if (j < C_CLS) {
            float m = -1e30f;
#pragma unroll
            for (int c = 0; c < C_CLS; c++) m = fmaxf(m, s_o[c]);
            float sum = 0.0f;
#pragma unroll
            for (int c = 0; c < C_CLS; c++) sum += __expf(s_o[c] - m);
            out[g * C_CLS + j] = s_o[j] - m - __logf(sum);
        }
        __syncthreads();   // protect smem reuse across loop iterations
    }
}

// ---------------------------------------------------------------------------
extern "C" void kernel_launch(void* const* d_in, const int* in_sizes, int n_in,
                              void* d_out, int out_size) {
    const float* x      = (const float*)d_in[0];   // [N, 64]
    const int*   eidx   = (const int*)d_in[1];     // [2, E]
    const float* ew     = (const float*)d_in[2];   // [E]
    const int*   batch  = (const int*)d_in[3];     // [N], sorted
    const float* conv_w = (const float*)d_in[4];
    const float* conv_b = (const float*)d_in[5];
    const float* lin1_w = (const float*)d_in[6];
    const float* lin1_b = (const float*)d_in[7];
    const float* lin2_w = (const float*)d_in[8];
    const float* lin2_b = (const float*)d_in[9];
    float* out = (float*)d_out;                    // [512, 10]

    sgc_persistent_kernel<<<NBLK, TPB>>>(x, eidx, ew, batch,
                                         conv_w, conv_b, lin1_w, lin1_b,
                                         lin2_w, lin2_b, out);
}

// round 13
// speedup vs baseline: 71.5381x; 1.1801x over previous
#include <cuda_runtime.h>
#include <math.h>

#define N_NODES   100000
#define N_EDGES   1600000
#define F_DIM     64
#define C_CLS     10
#define G_GRAPHS  512
#define CAP       64        // max in-degree (Poisson mean 16; P(>64) ~ 1e-20)
#define NBLK      592       // 148 SMs x 4 co-resident blocks (launch_bounds)
#define TPB       256
#define NWARPS    (NBLK * TPB / 32)
#define LEAVES    37        // tree barrier: 592 = 37 leaves x 16 blocks
#define LEAF_SZ   16

// Scratch (device globals: zero-initialized at module load; no runtime alloc)
__device__ float    g_h0[N_NODES * F_DIM];
__device__ float    g_h1[N_NODES * F_DIM];
__device__ float    g_dinv[N_NODES];
__device__ int      g_cnt_in[N_NODES];     // invariant: zero at kernel entry
__device__ int2     g_adj[(size_t)N_NODES * CAP];   // {src, raw weight bits}
__device__ float    g_s[G_GRAPHS * F_DIM]; // invariant: zero at kernel entry
__device__ unsigned g_leaf[LEAVES];        // monotonic; never reset
__device__ unsigned g_root;                // monotonic; never reset

static __device__ __forceinline__ void red_add_v4(float* dst, float4 v) {
    asm volatile("red.global.add.v4.f32 [%0], {%1, %2, %3, %4};"
                 :: "l"(dst), "f"(v.x), "f"(v.y), "f"(v.z), "f"(v.w)
                 : "memory");
}

// Two-level grid barrier, monotonic counters (no reset across graph replays).
// Arrivals: 16 serialized atomics per leaf (37 leaves in parallel) + 37 on
// the root, vs 592 serialized on one address for a flat barrier. The wait
// polls the root with a volatile LOAD (reads don't serialize at the LTS).
static __device__ __forceinline__ void grid_barrier() {
    __threadfence();                 // release (all threads)
    __syncthreads();
    if (threadIdx.x == 0) {
        int leaf = blockIdx.x >> 4;                       // 16 blocks / leaf
        unsigned t = atomicAdd(&g_leaf[leaf], 1u);
        unsigned round = t >> 4;
        if ((t & (LEAF_SZ - 1u)) == LEAF_SZ - 1u)         // last in leaf
            atomicAdd(&g_root, 1u);
        unsigned target = (round + 1u) * LEAVES;
        volatile unsigned* r = &g_root;
        while (*r < target) __nanosleep(32);
    }
    __syncthreads();
    __threadfence();                 // acquire (all threads)
}

// ---------------------------------------------------------------------------
// Hop in SCALED representation: input is h_hat = dinv .* h.
//   acc    = h_hat[c] + sum_e ew * h_hat[src]
//   !POOL: h_hat_out[c] = dinv[c]^2 * acc
//   POOL:  h_final[c]   = dinv[c]   * acc  -> red-add into g_s[batch[c]]
template <bool POOL>
static __device__ void hop_phase(const float* __restrict__ hin,
                                 float* __restrict__ hout,
                                 const int* __restrict__ batch) {
    int gwarp = (blockIdx.x * TPB + threadIdx.x) >> 5;
    int lane = threadIdx.x & 31;
    int half = lane >> 4;
    int sub = lane & 15;
    const float4* __restrict__ hin4 = reinterpret_cast<const float4*>(hin);
    float4* __restrict__ hout4 = reinterpret_cast<float4*>(hout);

    for (int base = gwarp * 2; base < N_NODES; base += NWARPS * 2) {
        int n = base + half;   // N_NODES even -> both halves always valid

        float dv = g_dinv[n];
        float4 acc = hin4[(size_t)n * 16 + sub];   // self contribution

        int cnt = min(g_cnt_in[n], CAP);
        const int2* adj = g_adj + (size_t)n * CAP;

        for (int k = 0; k < cnt; k += 4) {
            int4 p0 = *reinterpret_cast<const int4*>(adj + k);
            int4 p1 = *reinterpret_cast<const int4*>(adj + k + 2);
            int   s[4] = { p0.x, p0.z, p1.x, p1.z };
            float w[4] = { __int_as_float(p0.y), __int_as_float(p0.w),
                           __int_as_float(p1.y), __int_as_float(p1.w) };

            float4 u[4];
#pragma unroll
            for (int i = 0; i < 4; i++) {
                if (k + i >= cnt) w[i] = 0.0f;          // neutralize overshoot
                unsigned su = (unsigned)s[i];
                int src = (su < (unsigned)N_NODES) ? (int)su : 0;
                u[i] = hin4[(size_t)src * 16 + sub];    // 4 gathers in flight
            }
#pragma unroll
            for (int i = 0; i < 4; i++) {
                acc.x = fmaf(w[i], u[i].x, acc.x);
                acc.y = fmaf(w[i], u[i].y, acc.y);
                acc.z = fmaf(w[i], u[i].z, acc.z);
                acc.w = fmaf(w[i], u[i].w, acc.w);
            }
        }

        float sc = POOL ? dv : (dv * dv);
        acc.x *= sc; acc.y *= sc; acc.z *= sc; acc.w *= sc;

        if (POOL) {
            int b = batch[n];
            red_add_v4(&g_s[b * F_DIM + sub * 4], acc);
        } else {
            hout4[(size_t)n * 16 + sub] = acc;
        }
    }
}

// ---------------------------------------------------------------------------
// ONE persistent kernel. Entry invariant: g_cnt_in and g_s are all zero
// (zero-init at load; re-established at the tail of every call).
__global__ void __launch_bounds__(TPB, 4)
sgc_persistent_kernel(const float* __restrict__ x,
                      const int* __restrict__ eidx,
                      const float* __restrict__ ew,
                      const int* __restrict__ batch,
                      const float* __restrict__ conv_w,
                      const float* __restrict__ conv_b,
                      const float* __restrict__ lin1_w,
                      const float* __restrict__ lin1_b,
                      const float* __restrict__ lin2_w,
                      const float* __restrict__ lin2_b,
                      float* __restrict__ out) {
    const int tid = blockIdx.x * TPB + threadIdx.x;
    const int stride = NBLK * TPB;
    const int* row = eidx;             // edge_index[0]
    const int* col = eidx + N_EDGES;   // edge_index[1]

    // ---- phase 1: build in-adjacency buckets (counters pre-zeroed) ----
    for (int e = tid; e < N_EDGES; e += stride) {
        int c = col[e];
        int i = atomicAdd(&g_cnt_in[c], 1);
        if (i < CAP)
            g_adj[(size_t)c * CAP + i] = make_int2(row[e], __float_as_int(ew[e]));
    }
    grid_barrier();

    // ---- phase 2: degrees -> dinv, fused prescale h_hat0 = dinv*x -> g_h1
    {
        int gwarp = tid >> 5;
        int lane = threadIdx.x & 31;
        const float2* __restrict__ x2 = reinterpret_cast<const float2*>(x);
        float2* __restrict__ hp2 = reinterpret_cast<float2*>(g_h1);
        for (int n = gwarp; n < N_NODES; n += NWARPS) {
            int cnt = min(g_cnt_in[n], CAP);
            const int2* adj = g_adj + (size_t)n * CAP;
            float d = 0.0f;
            for (int k = lane; k < cnt; k += 32)
                d += __int_as_float(adj[k].y);
#pragma unroll
            for (int off = 16; off > 0; off >>= 1)
                d += __shfl_xor_sync(0xFFFFFFFFu, d, off);
            d += 1.0f;   // self loop
            float dv = (d > 0.0f) ? rsqrtf(d) : 0.0f;
            if (lane == 0) g_dinv[n] = dv;
            float2 v = x2[(size_t)n * 32 + lane];
            v.x *= dv; v.y *= dv;
            hp2[(size_t)n * 32 + lane] = v;
        }
    }
    grid_barrier();

    // ---- phases 3-5: K=3 propagation in scaled rep; hop 3 fuses pool ----
    hop_phase<false>(g_h1, g_h0, batch);   // h_hat0 -> h_hat1
    grid_barrier();
    hop_phase<false>(g_h0, g_h1, batch);   // h_hat1 -> h_hat2
    grid_barrier();
    hop_phase<true >(g_h1, g_h0 /*unused*/, batch);  // h_hat2 -> pooled h3
    grid_barrier();

    // ---- phase 6: head (grid-stride over graphs) + invariant restoration ----
    for (int g = blockIdx.x; g < G_GRAPHS; g += NBLK) {
        int j = threadIdx.x;

        __shared__ int   s_bounds[2];
        __shared__ float s_bufA[F_DIM];
        __shared__ float s_bufB[F_DIM];
        __shared__ float s_o[C_CLS];

        if (j < 2) {  // lower_bound(batch, g) / lower_bound(batch, g+1)
            int target = g + j;
            int lo = 0, hiN = N_NODES;
            while (lo < hiN) {
                int mid = (lo + hiN) >> 1;
                if (batch[mid] < target) lo = mid + 1; else hiN = mid;
            }
            s_bounds[j] = lo;
        }
        __syncthreads();

        if (j < F_DIM) {
            float cnt = (float)(s_bounds[1] - s_bounds[0]);
            s_bufA[j] = g_s[g * F_DIM + j] / fmaxf(cnt, 1.0f);   // mean
            g_s[g * F_DIM + j] = 0.0f;   // restore entry invariant for next call
        }
        __syncthreads();

        if (j < F_DIM) {
            float acc = conv_b[j];
#pragma unroll
            for (int f = 0; f < F_DIM; f++) acc += s_bufA[f] * conv_w[f * F_DIM + j];
            s_bufB[j] = acc;                                     // conv out
        }
        __syncthreads();

        if (j < F_DIM) {
            float acc = lin1_b[j];
#pragma unroll
            for (int f = 0; f < F_DIM; f++) acc += s_bufB[f] * lin1_w[f * F_DIM + j];
            s_bufA[j] = fmaxf(acc, 0.0f);                        // relu(lin1)
        }
        __syncthreads();

        if (j < C_CLS) {
            float acc = lin2_b[j];
#pragma unroll
            for (int f = 0; f < F_DIM; f++) acc += s_bufA[f] * lin2_w[f * C_CLS + j];
            s_o[j] = acc;
        }
        __syncthreads();

        if (j < C_CLS) {
            float m = -1e30f;
#pragma unroll
            for (int c = 0; c < C_CLS; c++) m = fmaxf(m, s_o[c]);
            float sum = 0.0f;
#pragma unroll
            for (int c = 0; c < C_CLS; c++) sum += __expf(s_o[c] - m);
            out[g * C_CLS + j] = s_o[j] - m - __logf(sum);
        }
        __syncthreads();   // protect smem reuse across loop iterations
    }

    // restore counter invariant for the next call (runs concurrently with
    // other blocks' head work; next kernel launch orders after this one)
    for (int i = tid; i < N_NODES; i += stride) g_cnt_in[i] = 0;
}

// ---------------------------------------------------------------------------
extern "C" void kernel_launch(void* const* d_in, const int* in_sizes, int n_in,
                              void* d_out, int out_size) {
    const float* x      = (const float*)d_in[0];   // [N, 64]
    const int*   eidx   = (const int*)d_in[1];     // [2, E]
    const float* ew     = (const float*)d_in[2];   // [E]
    const int*   batch  = (const int*)d_in[3];     // [N], sorted
    const float* conv_w = (const float*)d_in[4];
    const float* conv_b = (const float*)d_in[5];
    const float* lin1_w = (const float*)d_in[6];
    const float* lin1_b = (const float*)d_in[7];
    const float* lin2_w = (const float*)d_in[8];
    const float* lin2_b = (const float*)d_in[9];
    float* out = (float*)d_out;                    // [512, 10]

    sgc_persistent_kernel<<<NBLK, TPB>>>(x, eidx, ew, batch,
                                         conv_w, conv_b, lin1_w, lin1_b,
                                         lin2_w, lin2_b, out);
}